// round 1
// baseline (speedup 1.0000x reference)
#include <cuda_runtime.h>

namespace {
constexpr int NTOK = 256;   // N1 == N2 == 256
constexpr int DIM  = 1024;  // D
}

// Scratch (static __device__ globals: allocation-free, graph-safe)
__device__ float g_sim[3][NTOK * NTOK];   // 0: sim12, 1: sim11, 2: sim22
__device__ float g_part[24][NTOK * NTOK]; // split-k partials: z = m*8 + s
__device__ double g_loss;
__device__ unsigned long long g_pairs;
__device__ int g_selIsByte;

// ---------------------------------------------------------------------------
// Init: zero accumulators + sniff mask_sents dtype (bool bytes vs int32).
// For int32 {0,1} values, every byte at offset%4!=0 is zero. For a random
// 256-entry bool vector, some non-aligned byte is ~surely nonzero.
// ---------------------------------------------------------------------------
__global__ void init_kernel(const unsigned char* __restrict__ s1,
                            const unsigned char* __restrict__ s2) {
    g_loss = 0.0;
    g_pairs = 0ull;
    unsigned acc = 0u;
    for (int off = 0; off < NTOK; off++) {
        if ((off & 3) != 0) { acc |= s1[off]; acc |= s2[off]; }
    }
    g_selIsByte = (acc != 0u) ? 1 : 0;
}

// ---------------------------------------------------------------------------
// GEMM: C = A[256,1024] * B[256,1024]^T, fp32, 64x64 tiles, 4x4 per thread,
// split-k=8 into per-split partial buffers (deterministic).
// z = m*8 + s ;  m: 0 -> F1*F2^T, 1 -> F1*F1^T, 2 -> F2*F2^T
// ---------------------------------------------------------------------------
__global__ __launch_bounds__(256) void gemm_kernel(const float* __restrict__ f1,
                                                   const float* __restrict__ f2) {
    const int z = blockIdx.z;
    const int m = z >> 3;
    const int s = z & 7;
    const float* __restrict__ A = (m == 2) ? f2 : f1;
    const float* __restrict__ B = (m == 1) ? f1 : f2;
    const int rBase = blockIdx.y * 64;
    const int cBase = blockIdx.x * 64;

    __shared__ float sA[16][64];  // [k][row]
    __shared__ float sB[16][64];  // [k][col]

    const int tid = threadIdx.x;
    const int lr = tid >> 2;   // 0..63 row within tile (loader)
    const int lc = tid & 3;    // 0..3  float4 chunk within 16-wide k (loader)
    const int tx = tid & 15;   // compute col group
    const int ty = tid >> 4;   // compute row group

    float acc[4][4];
#pragma unroll
    for (int i = 0; i < 4; i++)
#pragma unroll
        for (int j = 0; j < 4; j++) acc[i][j] = 0.f;

    const int k0 = s * 128;
    for (int kc = 0; kc < 128; kc += 16) {
        const int kb = k0 + kc;
        const float4 av = *(const float4*)&A[(rBase + lr) * DIM + kb + lc * 4];
        const float4 bv = *(const float4*)&B[(cBase + lr) * DIM + kb + lc * 4];
        __syncthreads();
        sA[lc * 4 + 0][lr] = av.x;
        sA[lc * 4 + 1][lr] = av.y;
        sA[lc * 4 + 2][lr] = av.z;
        sA[lc * 4 + 3][lr] = av.w;
        sB[lc * 4 + 0][lr] = bv.x;
        sB[lc * 4 + 1][lr] = bv.y;
        sB[lc * 4 + 2][lr] = bv.z;
        sB[lc * 4 + 3][lr] = bv.w;
        __syncthreads();
#pragma unroll
        for (int k = 0; k < 16; k++) {
            const float4 a = *(const float4*)&sA[k][ty * 4];
            const float4 b = *(const float4*)&sB[k][tx * 4];
            const float ar[4] = {a.x, a.y, a.z, a.w};
            const float br[4] = {b.x, b.y, b.z, b.w};
#pragma unroll
            for (int i = 0; i < 4; i++)
#pragma unroll
                for (int j = 0; j < 4; j++)
                    acc[i][j] = __fmaf_rn(ar[i], br[j], acc[i][j]);
        }
    }

    float* __restrict__ C = g_part[z];
#pragma unroll
    for (int i = 0; i < 4; i++) {
        const int row = rBase + ty * 4 + i;
        float4 v = make_float4(acc[i][0], acc[i][1], acc[i][2], acc[i][3]);
        *(float4*)&C[row * NTOK + cBase + tx * 4] = v;
    }
}

// ---------------------------------------------------------------------------
// Reduce split-k partials into g_sim (fixed order => deterministic).
// ---------------------------------------------------------------------------
__global__ __launch_bounds__(256) void reduce_kernel() {
    const int gid = blockIdx.x * 256 + threadIdx.x;  // 0..196607
    const int m = gid >> 16;
    const int off = gid & 65535;
    float s = 0.f;
#pragma unroll
    for (int sp = 0; sp < 8; sp++) s += g_part[m * 8 + sp][off];
    g_sim[m][off] = s;
}

// ---------------------------------------------------------------------------
// Loss: one block per (term, row). 4 terms x 256 rows = 1024 blocks.
//   term 0: sim12 rows, mask_cross, sel1
//   term 1: sim12 cols, mask_cross^T, sel2
//   term 2: sim11 rows, mask1, sel1
//   term 3: sim22 rows, mask2, sel2
// Compacts pos/neg values (deterministic ballot prefix), then each thread
// covers a 16x16-strided (j,k) subgrid.
//   softplus(n - p) = max(n-p, 0) + log(1 + exp(-|n-p|))
// The log is amortized: one __logf per j via running product (1+e) factors.
// ---------------------------------------------------------------------------
__global__ __launch_bounds__(256) void loss_kernel(const int* __restrict__ mc,
                                                   const int* __restrict__ m1,
                                                   const int* __restrict__ m2,
                                                   const void* __restrict__ s1p,
                                                   const void* __restrict__ s2p) {
    const int r = blockIdx.x;
    const int t = r >> 8;
    const int i = r & 255;

    const void* selP = (t == 0 || t == 2) ? s1p : s2p;
    int sel;
    if (g_selIsByte) sel = ((const unsigned char*)selP)[i];
    else             sel = ((const int*)selP)[i];
    if (!sel) return;  // uniform across block

    __shared__ float sPos[256];
    __shared__ float sNeg[256];
    __shared__ int wPos[8];
    __shared__ float sRed[8];

    const int tid = threadIdx.x;
    const int lane = tid & 31;
    const int wid = tid >> 5;

    float v; int mk;
    if (t == 0)      { v = g_sim[0][i * 256 + tid]; mk = mc[i * 256 + tid]; }
    else if (t == 1) { v = g_sim[0][tid * 256 + i]; mk = mc[tid * 256 + i]; }
    else if (t == 2) { v = g_sim[1][i * 256 + tid]; mk = m1[i * 256 + tid]; }
    else             { v = g_sim[2][i * 256 + tid]; mk = m2[i * 256 + tid]; }

    const unsigned bp = __ballot_sync(0xffffffffu, mk != 0);
    if (lane == 0) wPos[wid] = __popc(bp);
    __syncthreads();

    int baseP = 0, P = 0;
#pragma unroll
    for (int w = 0; w < 8; w++) {
        const int c = wPos[w];
        if (w < wid) baseP += c;
        P += c;
    }
    const int N = 256 - P;
    const int baseN = wid * 32 - baseP;
    const unsigned lt = (1u << lane) - 1u;
    if (mk) sPos[baseP + __popc(bp & lt)] = v;
    else    sNeg[baseN + __popc(~bp & lt)] = v;
    __syncthreads();

    if (tid == 0)
        atomicAdd(&g_pairs, (unsigned long long)P * (unsigned long long)N);
    if (P == 0 || N == 0) return;  // uniform

    const int jj = tid >> 4;  // 0..15
    const int kk = tid & 15;  // 0..15
    float relu = 0.f;
    float lacc = 0.f;
    for (int j = jj; j < P; j += 16) {
        const float p = sPos[j];
        float prod = 1.f;  // at most 16 factors in [1,2] => <= 65536, no overflow
        for (int k = kk; k < N; k += 16) {
            const float x = sNeg[k] - p;
            relu += fmaxf(x, 0.f);
            const float e = __expf(-fabsf(x));
            prod = __fmaf_rn(prod, e, prod);  // prod *= (1 + e)
        }
        lacc += __logf(prod);
    }

    float total = relu + lacc;
#pragma unroll
    for (int o = 16; o; o >>= 1) total += __shfl_xor_sync(0xffffffffu, total, o);
    if (lane == 0) sRed[wid] = total;
    __syncthreads();
    if (tid == 0) {
        float bs = 0.f;
#pragma unroll
        for (int w = 0; w < 8; w++) bs += sRed[w];
        atomicAdd(&g_loss, (double)bs);
    }
}

__global__ void final_kernel(float* __restrict__ out) {
    const unsigned long long p = g_pairs;
    const double l = g_loss;
    out[0] = (float)((p > 0ull) ? (l / (double)p) : l);
}

// ---------------------------------------------------------------------------
// Inputs (setup_inputs order):
//  0 features1 f32[256,1024]   1 features2 f32[256,1024]
//  2 mask_cross i32[256,256]   3 mask1 i32[256,256]   4 mask2 i32[256,256]
//  5 mask_sents1 bool[256]     6 mask_sents2 bool[256]
// ---------------------------------------------------------------------------
extern "C" void kernel_launch(void* const* d_in, const int* in_sizes, int n_in,
                              void* d_out, int out_size) {
    const float* f1 = (const float*)d_in[0];
    const float* f2 = (const float*)d_in[1];
    const int* mc = (const int*)d_in[2];
    const int* m1 = (const int*)d_in[3];
    const int* m2 = (const int*)d_in[4];
    const unsigned char* s1 = (const unsigned char*)d_in[5];
    const unsigned char* s2 = (const unsigned char*)d_in[6];

    init_kernel<<<1, 1>>>(s1, s2);
    gemm_kernel<<<dim3(4, 4, 24), 256>>>(f1, f2);
    reduce_kernel<<<768, 256>>>();
    loss_kernel<<<1024, 256>>>(mc, m1, m2, (const void*)s1, (const void*)s2);
    final_kernel<<<1, 1>>>((float*)d_out);
}

// round 2
// speedup vs baseline: 1.1041x; 1.1041x over previous
#include <cuda_runtime.h>

namespace {
constexpr int NTOK = 256;   // N1 == N2 == 256
constexpr int DIM  = 1024;  // D
}

// Scratch (static __device__ globals: allocation-free, graph-safe)
__device__ float g_sim[3][NTOK * NTOK];   // 0: sim12, 1: sim11, 2: sim22
__device__ float g_part[24][NTOK * NTOK]; // split-k partials: z = m*8 + s
__device__ double g_loss;
__device__ unsigned long long g_pairs;
__device__ int g_selIsByte;

// ---------------------------------------------------------------------------
// Init: zero accumulators + sniff mask_sents dtype (bool bytes vs int32),
// PARALLEL (256 threads; the R1 version was 1 thread x ~512 serial LDGs).
// For int32 {0,1} values, every byte at offset%4!=0 is zero. For a random
// 256-entry bool vector, some non-aligned byte is ~surely nonzero.
// ---------------------------------------------------------------------------
__global__ __launch_bounds__(256) void init_kernel(const unsigned char* __restrict__ s1,
                                                   const unsigned char* __restrict__ s2) {
    const int t = threadIdx.x;
    int v = 0;
    if ((t & 3) != 0) v = (int)s1[t] | (int)s2[t];
    const int any = __syncthreads_or(v);
    if (t == 0) {
        g_loss = 0.0;
        g_pairs = 0ull;
        g_selIsByte = (any != 0) ? 1 : 0;
    }
}

// ---------------------------------------------------------------------------
// GEMM: C = A[256,1024] * B[256,1024]^T, fp32, 64x64 tiles, 4x4 per thread,
// split-k=8 into per-split partial buffers (deterministic).
// z = m*8 + s ;  m: 0 -> F1*F2^T, 1 -> F1*F1^T, 2 -> F2*F2^T
// ---------------------------------------------------------------------------
__global__ __launch_bounds__(256) void gemm_kernel(const float* __restrict__ f1,
                                                   const float* __restrict__ f2) {
    const int z = blockIdx.z;
    const int m = z >> 3;
    const int s = z & 7;
    const float* __restrict__ A = (m == 2) ? f2 : f1;
    const float* __restrict__ B = (m == 1) ? f1 : f2;
    const int rBase = blockIdx.y * 64;
    const int cBase = blockIdx.x * 64;

    __shared__ float sA[16][64];  // [k][row]
    __shared__ float sB[16][64];  // [k][col]

    const int tid = threadIdx.x;
    const int lr = tid >> 2;   // 0..63 row within tile (loader)
    const int lc = tid & 3;    // 0..3  float4 chunk within 16-wide k (loader)
    const int tx = tid & 15;   // compute col group
    const int ty = tid >> 4;   // compute row group

    float acc[4][4];
#pragma unroll
    for (int i = 0; i < 4; i++)
#pragma unroll
        for (int j = 0; j < 4; j++) acc[i][j] = 0.f;

    const int k0 = s * 128;
    for (int kc = 0; kc < 128; kc += 16) {
        const int kb = k0 + kc;
        const float4 av = *(const float4*)&A[(rBase + lr) * DIM + kb + lc * 4];
        const float4 bv = *(const float4*)&B[(cBase + lr) * DIM + kb + lc * 4];
        __syncthreads();
        sA[lc * 4 + 0][lr] = av.x;
        sA[lc * 4 + 1][lr] = av.y;
        sA[lc * 4 + 2][lr] = av.z;
        sA[lc * 4 + 3][lr] = av.w;
        sB[lc * 4 + 0][lr] = bv.x;
        sB[lc * 4 + 1][lr] = bv.y;
        sB[lc * 4 + 2][lr] = bv.z;
        sB[lc * 4 + 3][lr] = bv.w;
        __syncthreads();
#pragma unroll
        for (int k = 0; k < 16; k++) {
            const float4 a = *(const float4*)&sA[k][ty * 4];
            const float4 b = *(const float4*)&sB[k][tx * 4];
            const float ar[4] = {a.x, a.y, a.z, a.w};
            const float br[4] = {b.x, b.y, b.z, b.w};
#pragma unroll
            for (int i = 0; i < 4; i++)
#pragma unroll
                for (int j = 0; j < 4; j++)
                    acc[i][j] = __fmaf_rn(ar[i], br[j], acc[i][j]);
        }
    }

    float* __restrict__ C = g_part[z];
#pragma unroll
    for (int i = 0; i < 4; i++) {
        const int row = rBase + ty * 4 + i;
        float4 v = make_float4(acc[i][0], acc[i][1], acc[i][2], acc[i][3]);
        *(float4*)&C[row * NTOK + cBase + tx * 4] = v;
    }
}

// ---------------------------------------------------------------------------
// Reduce split-k partials into g_sim (fixed order => deterministic).
// ---------------------------------------------------------------------------
__global__ __launch_bounds__(256) void reduce_kernel() {
    const int gid = blockIdx.x * 256 + threadIdx.x;  // 0..196607
    const int m = gid >> 16;
    const int off = gid & 65535;
    float s = 0.f;
#pragma unroll
    for (int sp = 0; sp < 8; sp++) s += g_part[m * 8 + sp][off];
    g_sim[m][off] = s;
}

// ---------------------------------------------------------------------------
// Loss: one block per (term, row). 4 terms x 256 rows = 1024 blocks.
//   term 0: sim12 rows, mask_cross, sel1
//   term 1: sim12 cols, mask_cross^T, sel2
//   term 2: sim11 rows, mask1, sel1
//   term 3: sim22 rows, mask2, sel2
// Compacts pos/neg values (deterministic ballot prefix), pads both arrays to
// multiples of 32 with sentinel values that contribute exactly 0:
//   pos sentinel +1e30:  x = n - 1e30 = -1e30 -> relu 0, exp(-1e30)=0
//   neg sentinel -1e30:  x = -1e30 - p        -> relu 0, exp underflows to 0
// Threads arranged as 32 k-lanes x 8 j-groups; negs live in registers, one
// broadcast LDS of the pos per j step. softplus(n-p) = max(n-p,0) +
// log(1+e^{-|n-p|}); the log is amortized to one __logf per j step via a
// running product of (1+e) factors (<=32 factors in [1,2] => <= 2^32, safe).
// ---------------------------------------------------------------------------
__global__ __launch_bounds__(256) void loss_kernel(const int* __restrict__ mc,
                                                   const int* __restrict__ m1,
                                                   const int* __restrict__ m2,
                                                   const void* __restrict__ s1p,
                                                   const void* __restrict__ s2p) {
    const int r = blockIdx.x;
    const int t = r >> 8;
    const int i = r & 255;

    const void* selP = (t == 0 || t == 2) ? s1p : s2p;
    int sel;
    if (g_selIsByte) sel = ((const unsigned char*)selP)[i];
    else             sel = ((const int*)selP)[i];
    if (!sel) return;  // uniform across block

    __shared__ float sPos[256];
    __shared__ float sNeg[256];
    __shared__ int wPos[8];
    __shared__ float sRed[8];

    const int tid = threadIdx.x;
    const int lane = tid & 31;
    const int wid = tid >> 5;

    float v; int mk;
    if (t == 0)      { v = g_sim[0][i * 256 + tid]; mk = mc[i * 256 + tid]; }
    else if (t == 1) { v = g_sim[0][tid * 256 + i]; mk = mc[tid * 256 + i]; }
    else if (t == 2) { v = g_sim[1][i * 256 + tid]; mk = m1[i * 256 + tid]; }
    else             { v = g_sim[2][i * 256 + tid]; mk = m2[i * 256 + tid]; }

    const unsigned bp = __ballot_sync(0xffffffffu, mk != 0);
    if (lane == 0) wPos[wid] = __popc(bp);
    __syncthreads();

    int baseP = 0, P = 0;
#pragma unroll
    for (int w = 0; w < 8; w++) {
        const int c = wPos[w];
        if (w < wid) baseP += c;
        P += c;
    }
    const int N = 256 - P;
    const int baseN = wid * 32 - baseP;
    const unsigned lt = (1u << lane) - 1u;
    if (mk) sPos[baseP + __popc(bp & lt)] = v;
    else    sNeg[baseN + __popc(~bp & lt)] = v;
    __syncthreads();

    if (tid == 0)
        atomicAdd(&g_pairs, (unsigned long long)P * (unsigned long long)N);
    if (P == 0 || N == 0) return;  // uniform

    // Pad to multiples of 32 with zero-contribution sentinels.
    const int Ppad = (P + 31) & ~31;
    const int Npad = (N + 31) & ~31;
    if (tid >= P && tid < Ppad) sPos[tid] = 1e30f;
    if (tid >= N && tid < Npad) sNeg[tid] = -1e30f;
    __syncthreads();

    // 32 k-lanes x 8 j-groups; negs register-resident.
    const int kl = tid & 31;
    const int jg = tid >> 5;
    const int nb = Npad >> 5;  // 1..8 register blocks
    float nr[8];
#pragma unroll
    for (int u = 0; u < 8; u++)
        nr[u] = (u < nb) ? sNeg[kl + u * 32] : -1e30f;

    float relu = 0.f;
    float lacc = 0.f;
    for (int j = jg; j < Ppad; j += 8) {
        const float p = sPos[j];  // broadcast within warp (same jg)
        float prod = 1.f;
#pragma unroll 4
        for (int u = 0; u < nb; u++) {
            const float x = nr[u] - p;
            relu += fmaxf(x, 0.f);
            prod = __fmaf_rn(prod, __expf(-fabsf(x)), prod);  // *= (1+e)
        }
        lacc += __logf(prod);
    }

    float total = relu + lacc;
#pragma unroll
    for (int o = 16; o; o >>= 1) total += __shfl_xor_sync(0xffffffffu, total, o);
    if (lane == 0) sRed[wid] = total;
    __syncthreads();
    if (tid == 0) {
        float bs = 0.f;
#pragma unroll
        for (int w = 0; w < 8; w++) bs += sRed[w];
        atomicAdd(&g_loss, (double)bs);
    }
}

__global__ void final_kernel(float* __restrict__ out) {
    const unsigned long long p = g_pairs;
    const double l = g_loss;
    out[0] = (float)((p > 0ull) ? (l / (double)p) : l);
}

// ---------------------------------------------------------------------------
// Inputs (setup_inputs order):
//  0 features1 f32[256,1024]   1 features2 f32[256,1024]
//  2 mask_cross i32[256,256]   3 mask1 i32[256,256]   4 mask2 i32[256,256]
//  5 mask_sents1 bool[256]     6 mask_sents2 bool[256]
// ---------------------------------------------------------------------------
extern "C" void kernel_launch(void* const* d_in, const int* in_sizes, int n_in,
                              void* d_out, int out_size) {
    const float* f1 = (const float*)d_in[0];
    const float* f2 = (const float*)d_in[1];
    const int* mc = (const int*)d_in[2];
    const int* m1 = (const int*)d_in[3];
    const int* m2 = (const int*)d_in[4];
    const unsigned char* s1 = (const unsigned char*)d_in[5];
    const unsigned char* s2 = (const unsigned char*)d_in[6];

    init_kernel<<<1, 256>>>(s1, s2);
    gemm_kernel<<<dim3(4, 4, 24), 256>>>(f1, f2);
    reduce_kernel<<<768, 256>>>();
    loss_kernel<<<1024, 256>>>(mc, m1, m2, (const void*)s1, (const void*)s2);
    final_kernel<<<1, 1>>>((float*)d_out);
}

// round 4
// speedup vs baseline: 1.3801x; 1.2500x over previous
#include <cuda_runtime.h>
#include <cuda_bf16.h>
#include <cstdint>

namespace {
constexpr int NTOK = 256;
constexpr int DIM  = 1024;
}

// ---------------- scratch (static device globals, graph/alloc-safe) --------
__device__ float g_sim[3][NTOK * NTOK];       // 0: sim12, 1: sim11, 2: sim22
__device__ float g_part[24][NTOK * NTOK];     // split-k partials: z = m*8 + s
__device__ __nv_bfloat16 g_bf[4][NTOK * DIM]; // 0:hi1 1:lo1 2:hi2 3:lo2
__device__ double g_loss;
__device__ unsigned long long g_pairs;
__device__ int g_selIsByte;

// ---------------- helpers ---------------------------------------------------
__device__ __forceinline__ uint32_t smem_u32(const void* p) {
    uint32_t a;
    asm("{ .reg .u64 t; cvta.to.shared.u64 t, %1; cvt.u32.u64 %0, t; }" : "=r"(a) : "l"(p));
    return a;
}
__device__ __forceinline__ void ldsm4(uint32_t* r, uint32_t addr) {
    asm volatile("ldmatrix.sync.aligned.m8n8.x4.shared.b16 {%0,%1,%2,%3}, [%4];"
                 : "=r"(r[0]), "=r"(r[1]), "=r"(r[2]), "=r"(r[3]) : "r"(addr));
}
__device__ __forceinline__ void mma_bf16(float* c, const uint32_t* a, const uint32_t* b) {
    asm volatile("mma.sync.aligned.m16n8k16.row.col.f32.bf16.bf16.f32 "
                 "{%0,%1,%2,%3}, {%4,%5,%6,%7}, {%8,%9}, {%0,%1,%2,%3};"
                 : "+f"(c[0]), "+f"(c[1]), "+f"(c[2]), "+f"(c[3])
                 : "r"(a[0]), "r"(a[1]), "r"(a[2]), "r"(a[3]), "r"(b[0]), "r"(b[1]));
}

// ---------------------------------------------------------------------------
// Init: zero accumulators + sniff mask_sents dtype (bool bytes vs int32).
// ---------------------------------------------------------------------------
__global__ __launch_bounds__(256) void init_kernel(const unsigned char* __restrict__ s1,
                                                   const unsigned char* __restrict__ s2) {
    const int t = threadIdx.x;
    int v = 0;
    if ((t & 3) != 0) v = (int)s1[t] | (int)s2[t];
    const int any = __syncthreads_or(v);
    if (t == 0) {
        g_loss = 0.0;
        g_pairs = 0ull;
        g_selIsByte = (any != 0) ? 1 : 0;
    }
}

// ---------------------------------------------------------------------------
// Convert fp32 features -> (hi, lo) bf16 pair arrays.
// ---------------------------------------------------------------------------
__global__ __launch_bounds__(256) void convert_kernel(const float* __restrict__ f1,
                                                      const float* __restrict__ f2) {
    const int idx = blockIdx.x * 256 + threadIdx.x;   // 0..131071
    const int sel = idx >> 16;                        // 0: f1, 1: f2
    const int off = (idx & 65535) * 4;
    const float4 v = *(const float4*)&((sel ? f2 : f1)[off]);
    __nv_bfloat16 h0 = __float2bfloat16_rn(v.x);
    __nv_bfloat16 h1 = __float2bfloat16_rn(v.y);
    __nv_bfloat16 h2 = __float2bfloat16_rn(v.z);
    __nv_bfloat16 h3 = __float2bfloat16_rn(v.w);
    __nv_bfloat16 l0 = __float2bfloat16_rn(v.x - __bfloat162float(h0));
    __nv_bfloat16 l1 = __float2bfloat16_rn(v.y - __bfloat162float(h1));
    __nv_bfloat16 l2 = __float2bfloat16_rn(v.z - __bfloat162float(h2));
    __nv_bfloat16 l3 = __float2bfloat16_rn(v.w - __bfloat162float(h3));
    __nv_bfloat16* hd = g_bf[sel * 2];
    __nv_bfloat16* ld = g_bf[sel * 2 + 1];
    *(__nv_bfloat162*)&hd[off]     = __nv_bfloat162(h0, h1);
    *(__nv_bfloat162*)&hd[off + 2] = __nv_bfloat162(h2, h3);
    *(__nv_bfloat162*)&ld[off]     = __nv_bfloat162(l0, l1);
    *(__nv_bfloat162*)&ld[off + 2] = __nv_bfloat162(l2, l3);
}

// ---------------------------------------------------------------------------
// Tensor GEMM via mma.sync (works on plain compute_103 — tcgen05 does not).
// Block: 256 rows x 32 cols over one 128-wide k-split of one matrix term.
// grid = 192: blockIdx.x = ((m*8)+s)*8 + ct  (m matrix, s k-split, ct col/32)
// 8 warps, each 32 rows x 32 cols; bf16 split acc = hiA*hiB + hiA*loB + loA*hiB.
// SMEM staged in k-chunks of 32 halves, padded stride 40 halves (80B) ->
// ldmatrix conflict-free. Output: fp32 partials into g_part[m*8+s].
// ---------------------------------------------------------------------------
__global__ __launch_bounds__(256) void gemm_mma_kernel() {
    __shared__ __align__(16) __nv_bfloat16 sAh[256 * 40];
    __shared__ __align__(16) __nv_bfloat16 sAl[256 * 40];
    __shared__ __align__(16) __nv_bfloat16 sBh[32 * 40];
    __shared__ __align__(16) __nv_bfloat16 sBl[32 * 40];

    const int tid = threadIdx.x;
    const int lane = tid & 31;
    const int wid = tid >> 5;

    const int bz = blockIdx.x;
    const int ct = bz & 7;
    const int zz = bz >> 3;
    const int m = zz >> 3;
    const int s = zz & 7;
    const int cbase = ct * 32;
    const int k0 = s * 128;

    const __nv_bfloat16* __restrict__ Ah = g_bf[(m == 2) ? 2 : 0];
    const __nv_bfloat16* __restrict__ Al = g_bf[(m == 2) ? 3 : 1];
    const __nv_bfloat16* __restrict__ Bh = g_bf[(m == 1) ? 0 : 2];
    const __nv_bfloat16* __restrict__ Bl = g_bf[(m == 1) ? 1 : 3];

    const uint32_t uAh = smem_u32(sAh);
    const uint32_t uAl = smem_u32(sAl);
    const uint32_t uBh = smem_u32(sBh);
    const uint32_t uBl = smem_u32(sBl);

    // ldmatrix lane addressing (byte offsets within the padded tiles)
    const int rm = wid * 32;
    const int arow = lane & 15;
    const int acol = (lane >> 4) << 3;                 // 0 or 8
    // A offsets for m-tile mt, k16-step kk: ((rm + mt*16 + arow)*40 + acol + kk*16)*2
    const uint32_t aoff_base = (uint32_t)(((rm + arow) * 40 + acol) * 2);
    // B: i = lane&7, q = lane>>3: row = (q>>1)*8 + i, kh = (q&1)*8
    const int bi = lane & 7;
    const int bq = lane >> 3;
    const uint32_t boff_base = (uint32_t)(((((bq >> 1) << 3) + bi) * 40 + ((bq & 1) << 3)) * 2);

    float C[2][4][4];
#pragma unroll
    for (int mt = 0; mt < 2; mt++)
#pragma unroll
        for (int nt = 0; nt < 4; nt++)
#pragma unroll
            for (int q = 0; q < 4; q++) C[mt][nt][q] = 0.f;

#pragma unroll
    for (int chunk = 0; chunk < 4; chunk++) {
        const int kg = k0 + chunk * 32;
        __syncthreads();
        // Stage A: 256 rows x 32 halves (4 uint4 per row), hi + lo
#pragma unroll
        for (int it = 0; it < 4; it++) {
            const int v = tid + it * 256;              // 0..1023
            const int r = v >> 2;
            const int q = v & 3;
            const int g = r * DIM + kg + q * 8;
            const int o = r * 40 + q * 8;
            *(uint4*)&sAh[o] = *(const uint4*)&Ah[g];
            *(uint4*)&sAl[o] = *(const uint4*)&Al[g];
        }
        // Stage B: 32 rows (cols cbase..cbase+31) x 32 halves
        if (tid < 128) {
            const int r = tid >> 2;
            const int q = tid & 3;
            const int g = (cbase + r) * DIM + kg + q * 8;
            const int o = r * 40 + q * 8;
            *(uint4*)&sBh[o] = *(const uint4*)&Bh[g];
            *(uint4*)&sBl[o] = *(const uint4*)&Bl[g];
        }
        __syncthreads();

#pragma unroll
        for (int kk = 0; kk < 2; kk++) {
            const uint32_t ka = aoff_base + kk * 32;   // kk*16 halves
            const uint32_t kb = boff_base + kk * 32;
            uint32_t ah[2][4], al[2][4];
            ldsm4(ah[0], uAh + ka);
            ldsm4(ah[1], uAh + ka + 16 * 40 * 2);
            ldsm4(al[0], uAl + ka);
            ldsm4(al[1], uAl + ka + 16 * 40 * 2);
            uint32_t bh[8], bl[8];
            ldsm4(bh,     uBh + kb);
            ldsm4(bh + 4, uBh + kb + 16 * 40 * 2);
            ldsm4(bl,     uBl + kb);
            ldsm4(bl + 4, uBl + kb + 16 * 40 * 2);
#pragma unroll
            for (int mt = 0; mt < 2; mt++)
#pragma unroll
                for (int nt = 0; nt < 4; nt++) {
                    mma_bf16(C[mt][nt], ah[mt], &bh[nt * 2]);
                    mma_bf16(C[mt][nt], ah[mt], &bl[nt * 2]);
                    mma_bf16(C[mt][nt], al[mt], &bh[nt * 2]);
                }
        }
    }

    // Epilogue: write fp32 partials (deterministic split-k buffers)
    float* __restrict__ dst = g_part[m * 8 + s];
    const int erow = lane >> 2;
    const int ecol = (lane & 3) * 2;
#pragma unroll
    for (int mt = 0; mt < 2; mt++)
#pragma unroll
        for (int nt = 0; nt < 4; nt++) {
            const int r0 = rm + mt * 16 + erow;
            const int cc = cbase + nt * 8 + ecol;
            *(float2*)&dst[r0 * NTOK + cc] = make_float2(C[mt][nt][0], C[mt][nt][1]);
            *(float2*)&dst[(r0 + 8) * NTOK + cc] = make_float2(C[mt][nt][2], C[mt][nt][3]);
        }
}

// ---------------------------------------------------------------------------
// Reduce split-k partials into g_sim (fixed order => deterministic).
// ---------------------------------------------------------------------------
__global__ __launch_bounds__(256) void reduce_kernel() {
    const int gid = blockIdx.x * 256 + threadIdx.x;  // 0..196607
    const int m = gid >> 16;
    const int off = gid & 65535;
    float s = 0.f;
#pragma unroll
    for (int sp = 0; sp < 8; sp++) s += g_part[m * 8 + sp][off];
    g_sim[m][off] = s;
}

// ---------------------------------------------------------------------------
// Loss: one block per (term, row). Compacted pos/neg with sentinels padded to
// multiples of 32. Templated on NB = Npad/32 so neg values are truly
// register-resident (R2's dynamically-indexed nr[] spilled to local memory).
// Two interleaved product chains halve the FFMA dependency.
// ---------------------------------------------------------------------------
template <int NB>
__device__ __forceinline__ float row_loss(const float* __restrict__ sPos,
                                          const float* __restrict__ sNeg,
                                          int Ppad, int kl, int jg) {
    float nr[NB];
#pragma unroll
    for (int u = 0; u < NB; u++) nr[u] = sNeg[kl + u * 32];
    float relu = 0.f, lacc = 0.f;
    for (int j = jg; j < Ppad; j += 8) {
        const float p = sPos[j];
        float prodA = 1.f, prodB = 1.f;
#pragma unroll
        for (int u = 0; u < NB; u++) {
            const float x = nr[u] - p;
            relu += fmaxf(x, 0.f);
            const float e = __expf(-fabsf(x));
            if (u & 1) prodB = __fmaf_rn(prodB, e, prodB);
            else       prodA = __fmaf_rn(prodA, e, prodA);
        }
        lacc += __logf(prodA) + __logf(prodB);
    }
    return relu + lacc;
}

__global__ __launch_bounds__(256) void loss_kernel(const int* __restrict__ mc,
                                                   const int* __restrict__ m1,
                                                   const int* __restrict__ m2,
                                                   const void* __restrict__ s1p,
                                                   const void* __restrict__ s2p) {
    const int r = blockIdx.x;
    const int t = r >> 8;
    const int i = r & 255;

    const void* selP = (t == 0 || t == 2) ? s1p : s2p;
    int sel;
    if (g_selIsByte) sel = ((const unsigned char*)selP)[i];
    else             sel = ((const int*)selP)[i];
    if (!sel) return;

    __shared__ float sPos[256];
    __shared__ float sNeg[256];
    __shared__ int wPos[8];
    __shared__ float sRed[8];

    const int tid = threadIdx.x;
    const int lane = tid & 31;
    const int wid = tid >> 5;

    float v; int mk;
    if (t == 0)      { v = g_sim[0][i * 256 + tid]; mk = mc[i * 256 + tid]; }
    else if (t == 1) { v = g_sim[0][tid * 256 + i]; mk = mc[tid * 256 + i]; }
    else if (t == 2) { v = g_sim[1][i * 256 + tid]; mk = m1[i * 256 + tid]; }
    else             { v = g_sim[2][i * 256 + tid]; mk = m2[i * 256 + tid]; }

    const unsigned bp = __ballot_sync(0xffffffffu, mk != 0);
    if (lane == 0) wPos[wid] = __popc(bp);
    __syncthreads();

    int baseP = 0, P = 0;
#pragma unroll
    for (int w = 0; w < 8; w++) {
        const int c = wPos[w];
        if (w < wid) baseP += c;
        P += c;
    }
    const int N = 256 - P;
    const int baseN = wid * 32 - baseP;
    const unsigned lt = (1u << lane) - 1u;
    if (mk) sPos[baseP + __popc(bp & lt)] = v;
    else    sNeg[baseN + __popc(~bp & lt)] = v;
    __syncthreads();

    if (tid == 0)
        atomicAdd(&g_pairs, (unsigned long long)P * (unsigned long long)N);
    if (P == 0 || N == 0) return;

    const int Ppad = (P + 31) & ~31;
    const int Npad = (N + 31) & ~31;
    if (tid >= P && tid < Ppad) sPos[tid] = 1e30f;
    if (tid >= N && tid < Npad) sNeg[tid] = -1e30f;
    __syncthreads();

    const int kl = tid & 31;
    const int jg = tid >> 5;
    float total;
    switch (Npad >> 5) {
        case 1: total = row_loss<1>(sPos, sNeg, Ppad, kl, jg); break;
        case 2: total = row_loss<2>(sPos, sNeg, Ppad, kl, jg); break;
        case 3: total = row_loss<3>(sPos, sNeg, Ppad, kl, jg); break;
        case 4: total = row_loss<4>(sPos, sNeg, Ppad, kl, jg); break;
        case 5: total = row_loss<5>(sPos, sNeg, Ppad, kl, jg); break;
        case 6: total = row_loss<6>(sPos, sNeg, Ppad, kl, jg); break;
        case 7: total = row_loss<7>(sPos, sNeg, Ppad, kl, jg); break;
        default: total = row_loss<8>(sPos, sNeg, Ppad, kl, jg); break;
    }

#pragma unroll
    for (int o = 16; o; o >>= 1) total += __shfl_xor_sync(0xffffffffu, total, o);
    if (lane == 0) sRed[wid] = total;
    __syncthreads();
    if (tid == 0) {
        float bs = 0.f;
#pragma unroll
        for (int w = 0; w < 8; w++) bs += sRed[w];
        atomicAdd(&g_loss, (double)bs);
    }
}

__global__ void final_kernel(float* __restrict__ out) {
    const unsigned long long p = g_pairs;
    const double l = g_loss;
    out[0] = (float)((p > 0ull) ? (l / (double)p) : l);
}

// ---------------------------------------------------------------------------
// Inputs: 0 f1 f32[256,1024]  1 f2 f32[256,1024]  2 mask_cross i32[256,256]
//         3 mask1 i32[256,256] 4 mask2 i32[256,256] 5/6 mask_sents bool[256]
// ---------------------------------------------------------------------------
extern "C" void kernel_launch(void* const* d_in, const int* in_sizes, int n_in,
                              void* d_out, int out_size) {
    const float* f1 = (const float*)d_in[0];
    const float* f2 = (const float*)d_in[1];
    const int* mc = (const int*)d_in[2];
    const int* m1 = (const int*)d_in[3];
    const int* m2 = (const int*)d_in[4];
    const unsigned char* s1 = (const unsigned char*)d_in[5];
    const unsigned char* s2 = (const unsigned char*)d_in[6];

    init_kernel<<<1, 256>>>(s1, s2);
    convert_kernel<<<512, 256>>>(f1, f2);
    gemm_mma_kernel<<<192, 256>>>();
    reduce_kernel<<<768, 256>>>();
    loss_kernel<<<1024, 256>>>(mc, m1, m2, (const void*)s1, (const void*)s2);
    final_kernel<<<1, 1>>>((float*)d_out);
}